// round 5
// baseline (speedup 1.0000x reference)
#include <cuda_runtime.h>
#include <cstddef>

// Problem constants (fixed by reference: B=16, N=M=1024, D=32)
#define BB    16
#define NN    1024
#define ROWS  (BB * NN)          // 16384 dual variables per side
#define CELEM (BB * NN * NN)     // 16,777,216 cost entries

// eps = 1e-3
#define K2F       1442.6951f      // log2(e)/eps  : nat-exponent -> base-2 exponent scale
#define EPSLN2F   6.9314718e-4f   // eps*ln(2)
#define EPSLOGMU  (-6.9314616e-3f) // eps * log(1/1024 + 1e-8)   (log_nu identical, N==M)
#define SKIP_MARGIN 0.03f          // terms below max-0.03 contribute < 2^-43 to the LSE sum

// Scratch (device globals: allocation-free rule)
__device__ float g_C [CELEM];    // C[b][i][j], row-major            (64 MB)
__device__ float g_CT[CELEM];    // C[b][j][i] (transposed copy)     (64 MB)
__device__ float g_u [ROWS];
__device__ float g_v [ROWS];
__device__ float g_du[ROWS];
__device__ float g_row[ROWS];
__device__ int   g_done;

// ---------------------------------------------------------------------------
// Reset state (graph is replayed many times; everything must re-init)
// ---------------------------------------------------------------------------
__global__ void k_init() {
    int i = blockIdx.x * blockDim.x + threadIdx.x;
    if (i < ROWS) { g_u[i] = 0.f; g_v[i] = 0.f; }
    if (i == 0)   g_done = 0;
}

// ---------------------------------------------------------------------------
// Cost matrix: C[b][i][j] = sum_d (x[b][i][d] - y[b][j][d])^2, plus transpose.
// One block per (b, 32x32 tile). smem-staged, conflict-free (pad 33).
// FIX (R3): stage ALL 32 rows of each tile (4 rows per thread), not 8.
// ---------------------------------------------------------------------------
__global__ void __launch_bounds__(256) k_cost(const float* __restrict__ X,
                                              const float* __restrict__ Y) {
    __shared__ float xs[32][33], ys[32][33], cs[32][33];
    int t  = blockIdx.x;
    int b  = t >> 10;
    int it = (t >> 5) & 31;     // i-tile
    int jt = t & 31;            // j-tile
    int tid = threadIdx.x;
    int r = tid >> 5, d = tid & 31;   // r in 0..7, d in 0..31

#pragma unroll
    for (int k = 0; k < 4; k++) {
        int rr = r + (k << 3);        // rows 0..31, coalesced on d
        xs[rr][d] = X[((size_t)b * 1024 + it * 32 + rr) * 32 + d];
        ys[rr][d] = Y[((size_t)b * 1024 + jt * 32 + rr) * 32 + d];
    }
    __syncthreads();

    int tx = tid & 31, ty = tid >> 5;     // ty in 0..7
#pragma unroll
    for (int k = 0; k < 4; k++) {
        int i = ty * 4 + k;
        float acc = 0.f;
#pragma unroll
        for (int dd = 0; dd < 32; dd++) {
            float diff = xs[i][dd] - ys[tx][dd];
            acc = fmaf(diff, diff, acc);
        }
        cs[i][tx] = acc;
    }
    __syncthreads();

    size_t cbase = (size_t)b << 20;
#pragma unroll
    for (int k = 0; k < 4; k++) {
        int i = ty * 4 + k;
        // C: row i0+i, cols jt*32 + tx  (coalesced)
        g_C [cbase + (size_t)(it * 32 + i) * 1024 + jt * 32 + tx] = cs[i][tx];
        // CT: row j0+i, cols it*32 + tx (coalesced; cs[tx][i] conflict-free w/ pad)
        g_CT[cbase + (size_t)(jt * 32 + i) * 1024 + it * 32 + tx] = cs[tx][i];
    }
}

// ---------------------------------------------------------------------------
// One Sinkhorn half-step. mode 0: u-update (rows of C, dual v, writes u + du)
//                         mode 1: v-update (rows of CT, dual u, writes v)
// One warp per row (1024 elems): exact max scan + group-skip exp pass.
//   z_new = eps*log_mu - m - eps*ln(sum_j exp((val_j - m)/eps)),  val_j = w_j - C_rj
// ---------------------------------------------------------------------------
__global__ void __launch_bounds__(256) k_lse(int mode) {
    if (g_done) return;
    int row  = (blockIdx.x << 3) + (threadIdx.x >> 5);
    int lane = threadIdx.x & 31;

    const float* base = (mode == 0) ? g_C : g_CT;
    const float* wsrc = (mode == 0) ? g_v : g_u;
    const float4* c4 = reinterpret_cast<const float4*>(base + ((size_t)row << 10));
    const float4* w4 = reinterpret_cast<const float4*>(wsrc + (size_t)(row & ~1023));

    float val[32];
    float gm[8];
#pragma unroll
    for (int g = 0; g < 8; g++) {
        float4 c = c4[lane + (g << 5)];
        float4 w = w4[lane + (g << 5)];
        int o = g << 2;
        val[o]     = w.x - c.x;
        val[o + 1] = w.y - c.y;
        val[o + 2] = w.z - c.z;
        val[o + 3] = w.w - c.w;
        gm[g] = fmaxf(fmaxf(val[o], val[o + 1]), fmaxf(val[o + 2], val[o + 3]));
    }
    float m = gm[0];
#pragma unroll
    for (int g = 1; g < 8; g++) m = fmaxf(m, gm[g]);
#pragma unroll
    for (int off = 16; off > 0; off >>= 1)
        m = fmaxf(m, __shfl_xor_sync(0xffffffffu, m, off));

    float thr = m - SKIP_MARGIN;
    float s = 0.f;
#pragma unroll
    for (int g = 0; g < 8; g++) {
        if (gm[g] > thr) {          // rare: only groups containing near-max terms
            int o = g << 2;
            s += exp2f((val[o]     - m) * K2F);
            s += exp2f((val[o + 1] - m) * K2F);
            s += exp2f((val[o + 2] - m) * K2F);
            s += exp2f((val[o + 3] - m) * K2F);
        }
    }
#pragma unroll
    for (int off = 16; off > 0; off >>= 1)
        s += __shfl_xor_sync(0xffffffffu, s, off);

    if (lane == 0) {
        float z = EPSLOGMU - m - EPSLN2F * log2f(s);
        if (mode == 0) {
            float old = g_u[row];
            g_u[row]  = z;
            g_du[row] = fabsf(z - old);
        } else {
            g_v[row]  = z;
        }
    }
}

// ---------------------------------------------------------------------------
// err = (1/B) * sum |du|; latch g_done if err < 0.1. Deterministic fixed tree.
// ---------------------------------------------------------------------------
__global__ void k_err() {
    if (g_done) return;
    __shared__ float sm[256];
    float s = 0.f;
    for (int k = threadIdx.x; k < ROWS; k += 256) s += g_du[k];
    sm[threadIdx.x] = s;
    __syncthreads();
    for (int h = 128; h > 0; h >>= 1) {
        if (threadIdx.x < h) sm[threadIdx.x] += sm[threadIdx.x + h];
        __syncthreads();
    }
    if (threadIdx.x == 0) {
        float err = sm[0] * (1.0f / 16.0f);
        if (err < 0.1f) g_done = 1;
    }
}

// ---------------------------------------------------------------------------
// Final: row partials of sum_j exp((u_i + v_j - C_ij)/eps) * C_ij
// Same warp-per-row scan with group-skip (cutoff 2^-40 per term).
// ---------------------------------------------------------------------------
__global__ void __launch_bounds__(256) k_final() {
    int row  = (blockIdx.x << 3) + (threadIdx.x >> 5);
    int lane = threadIdx.x & 31;
    const float4* c4 = reinterpret_cast<const float4*>(g_C + ((size_t)row << 10));
    const float4* w4 = reinterpret_cast<const float4*>(g_v + (size_t)(row & ~1023));
    float uk = g_u[row];

    float val[32], cc[32];
    float gm[8];
#pragma unroll
    for (int g = 0; g < 8; g++) {
        float4 c = c4[lane + (g << 5)];
        float4 w = w4[lane + (g << 5)];
        int o = g << 2;
        cc[o] = c.x; cc[o + 1] = c.y; cc[o + 2] = c.z; cc[o + 3] = c.w;
        val[o]     = w.x - c.x;
        val[o + 1] = w.y - c.y;
        val[o + 2] = w.z - c.z;
        val[o + 3] = w.w - c.w;
        gm[g] = fmaxf(fmaxf(val[o], val[o + 1]), fmaxf(val[o + 2], val[o + 3]));
    }
    // term visible iff (val + uk)/eps > -40/log2(e)  <=>  val > -40*eps*ln2 - uk
    float thr = -40.0f * EPSLN2F - uk;
    float s = 0.f;
#pragma unroll
    for (int g = 0; g < 8; g++) {
        if (gm[g] > thr) {
            int o = g << 2;
            s += exp2f((val[o]     + uk) * K2F) * cc[o];
            s += exp2f((val[o + 1] + uk) * K2F) * cc[o + 1];
            s += exp2f((val[o + 2] + uk) * K2F) * cc[o + 2];
            s += exp2f((val[o + 3] + uk) * K2F) * cc[o + 3];
        }
    }
#pragma unroll
    for (int off = 16; off > 0; off >>= 1)
        s += __shfl_xor_sync(0xffffffffu, s, off);
    if (lane == 0) g_row[row] = s;
}

__global__ void k_out(float* __restrict__ out) {
    __shared__ float sm[256];
    float s = 0.f;
    for (int k = threadIdx.x; k < ROWS; k += 256) s += g_row[k];
    sm[threadIdx.x] = s;
    __syncthreads();
    for (int h = 128; h > 0; h >>= 1) {
        if (threadIdx.x < h) sm[threadIdx.x] += sm[threadIdx.x + h];
        __syncthreads();
    }
    if (threadIdx.x == 0) out[0] = sm[0] * (1.0f / 16.0f);   // mean over B of per-batch sums
}

// ---------------------------------------------------------------------------
extern "C" void kernel_launch(void* const* d_in, const int* in_sizes, int n_in,
                              void* d_out, int out_size) {
    (void)in_sizes; (void)n_in; (void)out_size;
    const float* X = (const float*)d_in[0];   // output [16,1024,32]
    const float* Y = (const float*)d_in[1];   // labels [16,1024,32]

    k_init<<<64, 256>>>();
    k_cost<<<16384, 256>>>(X, Y);

    for (int it = 0; it < 100; it++) {
        k_lse<<<2048, 256>>>(0);   // u-update (+ du)
        k_lse<<<2048, 256>>>(1);   // v-update (uses fresh u)
        k_err<<<1, 256>>>();       // convergence latch
    }

    k_final<<<2048, 256>>>();
    k_out<<<1, 256>>>((float*)d_out);
}

// round 6
// speedup vs baseline: 1.5426x; 1.5426x over previous
#include <cuda_runtime.h>
#include <cuda_fp16.h>
#include <cstddef>

// Problem constants (B=16, N=M=1024, D=32)
#define CELEM (16 * 1024 * 1024)
#define ROWS  (16 * 1024)
#define NBLK  128                  // persistent blocks (<= SM count, co-resident)

// eps = 1e-3
#define K2F       1442.6951f       // log2(e)/eps
#define EPSLN2F   6.9314718e-4f    // eps*ln2
#define EPSLOGMU  (-6.9314616e-3f) // eps*log(1/1024 + 1e-8)
#define MARGIN    0.6f             // fp16 prefilter margin (covers 2*(0.125+0.03+0.0625)+0.03)

// Device scratch (allocation-free rule)
__device__ float  g_C  [CELEM];    // fp32 C  (exact pass + final)
__device__ float  g_CT [CELEM];    // fp32 C^T
__device__ __half g_Ch [CELEM];    // fp16 C  (prefilter scan)
__device__ __half g_CTh[CELEM];    // fp16 C^T
__device__ float  g_u[ROWS], g_v[ROWS];
__device__ float  g_bp[NBLK];
__device__ int    g_done;
__device__ int    g_bar_count;
__device__ volatile int g_bar_gen;

// ---------------------------------------------------------------------------
// Software global barrier across NBLK co-resident blocks.
// __threadfence = fence.sc.gpu -> CCTL.IVALL (L1 flush) => cross-SM visibility.
// ---------------------------------------------------------------------------
__device__ __forceinline__ void gbarrier() {
    __syncthreads();
    if (threadIdx.x == 0) {
        __threadfence();                       // release: publish this block's writes
        int gen = g_bar_gen;
        if (atomicAdd(&g_bar_count, 1) == NBLK - 1) {
            g_bar_count = 0;
            __threadfence();
            g_bar_gen = gen + 1;               // release all waiters
        } else {
            while (g_bar_gen == gen) __nanosleep(64);
        }
        __threadfence();                       // acquire: invalidate stale L1
    }
    __syncthreads();
}

__device__ __forceinline__ float wred_max(float v) {
#pragma unroll
    for (int o = 16; o; o >>= 1) v = fmaxf(v, __shfl_xor_sync(0xffffffffu, v, o));
    return v;
}
__device__ __forceinline__ float wred_sum(float v) {
#pragma unroll
    for (int o = 16; o; o >>= 1) v += __shfl_xor_sync(0xffffffffu, v, o);
    return v;
}

// fp16 prefilter of group Q (8 elements): DST = max_j (w_j - C_rj) in half precision
#define PREF_GRP(Q, DST) do {                                                   \
    uint4 cq = cp[((Q) << 5) + lane];                                           \
    half2 d0 = __hsub2(w2[(Q)*4+0], *reinterpret_cast<const half2*>(&cq.x));    \
    half2 d1 = __hsub2(w2[(Q)*4+1], *reinterpret_cast<const half2*>(&cq.y));    \
    half2 d2 = __hsub2(w2[(Q)*4+2], *reinterpret_cast<const half2*>(&cq.z));    \
    half2 d3 = __hsub2(w2[(Q)*4+3], *reinterpret_cast<const half2*>(&cq.w));    \
    half2 mx = __hmax2(__hmax2(d0, d1), __hmax2(d2, d3));                       \
    DST = fmaxf(__low2float(mx), __high2float(mx));                             \
} while (0)

#define BUILD_W2() do {                                                         \
    _Pragma("unroll")                                                           \
    for (int q = 0; q < 4; q++) {                                               \
        float4 wa = ws4[(q << 6) + (lane << 1)];                                \
        float4 wb = ws4[(q << 6) + (lane << 1) + 1];                            \
        w2[q*4+0] = __floats2half2_rn(wa.x, wa.y);                              \
        w2[q*4+1] = __floats2half2_rn(wa.z, wa.w);                              \
        w2[q*4+2] = __floats2half2_rn(wb.x, wb.y);                              \
        w2[q*4+3] = __floats2half2_rn(wb.z, wb.w);                              \
    }                                                                           \
} while (0)

// ---------------------------------------------------------------------------
// Cost matrix: C[b][i][j] = ||x_i - y_j||^2, fp32 + fp16, plus transposes.
// (verified in R5; fp16 stores added)
// ---------------------------------------------------------------------------
__global__ void __launch_bounds__(256) k_cost(const float* __restrict__ X,
                                              const float* __restrict__ Y) {
    __shared__ float xs[32][33], ys[32][33], cs[32][33];
    int t  = blockIdx.x;
    int b  = t >> 10;
    int it = (t >> 5) & 31;
    int jt = t & 31;
    int tid = threadIdx.x;
    int r = tid >> 5, d = tid & 31;

#pragma unroll
    for (int k = 0; k < 4; k++) {
        int rr = r + (k << 3);
        xs[rr][d] = X[((size_t)b * 1024 + it * 32 + rr) * 32 + d];
        ys[rr][d] = Y[((size_t)b * 1024 + jt * 32 + rr) * 32 + d];
    }
    __syncthreads();

    int tx = tid & 31, ty = tid >> 5;
#pragma unroll
    for (int k = 0; k < 4; k++) {
        int i = ty * 4 + k;
        float acc = 0.f;
#pragma unroll
        for (int dd = 0; dd < 32; dd++) {
            float diff = xs[i][dd] - ys[tx][dd];
            acc = fmaf(diff, diff, acc);
        }
        cs[i][tx] = acc;
    }
    __syncthreads();

    size_t cbase = (size_t)b << 20;
#pragma unroll
    for (int k = 0; k < 4; k++) {
        int i = ty * 4 + k;
        size_t idx  = cbase + (size_t)(it * 32 + i) * 1024 + jt * 32 + tx;
        size_t idxT = cbase + (size_t)(jt * 32 + i) * 1024 + it * 32 + tx;
        float  cv  = cs[i][tx];
        float  cvT = cs[tx][i];
        g_C  [idx]  = cv;
        g_CT [idxT] = cvT;
        g_Ch [idx]  = __float2half_rn(cv);
        g_CTh[idxT] = __float2half_rn(cvT);
    }
}

// ---------------------------------------------------------------------------
// One half-step for this block's 128 rows.
// fp16 prefilter -> exact fp32 max -> exact exp-sum (flagged groups only).
// MODE0: writes u + per-block |du| partial into g_bp.
// ---------------------------------------------------------------------------
template <bool MODE0>
__device__ __forceinline__ void scan_phase(
    int bid, int tid, int lane, int wid,
    const __half* __restrict__ Ch, const float* __restrict__ Cf,
    const float* __restrict__ wsrc, float* __restrict__ zdst,
    float* ws, float* du_s)
{
    int b = bid >> 3;                       // batch of this block's 128 rows
    ws[tid] = wsrc[(b << 10) + tid];        // stage dual vector (fp32)
    __syncthreads();

    const float4* ws4 = (const float4*)ws;
    half2 w2[16];
    BUILD_W2();

#pragma unroll 1
    for (int r = 0; r < 4; r++) {
        int rl  = (wid << 2) + r;
        int row = (bid << 7) + rl;
        const uint4*  cp  = (const uint4*) (Ch + ((size_t)row << 10));
        const float4* cf4 = (const float4*)(Cf + ((size_t)row << 10));

        float gm0, gm1, gm2, gm3;
        PREF_GRP(0, gm0); PREF_GRP(1, gm1); PREF_GRP(2, gm2); PREF_GRP(3, gm3);

        float mrow = wred_max(fmaxf(fmaxf(gm0, gm1), fmaxf(gm2, gm3)));
        float thr  = mrow - MARGIN;
        int msk = (gm0 > thr) | ((gm1 > thr) << 1) | ((gm2 > thr) << 2) | ((gm3 > thr) << 3);

        // exact max over flagged groups (argmax group is guaranteed flagged)
        float me = -3.4e38f;
#pragma unroll 1
        for (int q = 0; q < 4; q++) if ((msk >> q) & 1) {
            int ix = (q << 6) + (lane << 1);
            float4 a  = cf4[ix],  bb = cf4[ix + 1];
            float4 wa = ws4[ix],  wb = ws4[ix + 1];
            me = fmaxf(me, fmaxf(fmaxf(wa.x - a.x,  wa.y - a.y),
                                 fmaxf(wa.z - a.z,  wa.w - a.w)));
            me = fmaxf(me, fmaxf(fmaxf(wb.x - bb.x, wb.y - bb.y),
                                 fmaxf(wb.z - bb.z, wb.w - bb.w)));
        }
        me = wred_max(me);

        float s = 0.f;
#pragma unroll 1
        for (int q = 0; q < 4; q++) if ((msk >> q) & 1) {
            int ix = (q << 6) + (lane << 1);
            float4 a  = cf4[ix],  bb = cf4[ix + 1];   // L1 hit (just loaded)
            float4 wa = ws4[ix],  wb = ws4[ix + 1];
            s += exp2f((wa.x - a.x  - me) * K2F) + exp2f((wa.y - a.y  - me) * K2F)
               + exp2f((wa.z - a.z  - me) * K2F) + exp2f((wa.w - a.w  - me) * K2F)
               + exp2f((wb.x - bb.x - me) * K2F) + exp2f((wb.y - bb.y - me) * K2F)
               + exp2f((wb.z - bb.z - me) * K2F) + exp2f((wb.w - bb.w - me) * K2F);
        }
        s = wred_sum(s);

        if (lane == 0) {
            float z = EPSLOGMU - me - EPSLN2F * log2f(s);
            if (MODE0) du_s[rl] = fabsf(z - zdst[row]);
            zdst[row] = z;
        }
    }

    if (MODE0) {
        __syncthreads();
        if (wid == 0) {
            float e = du_s[lane] + du_s[lane + 32] + du_s[lane + 64] + du_s[lane + 96];
            e = wred_sum(e);
            if (lane == 0) g_bp[bid] = e;
        }
    }
}

// ---------------------------------------------------------------------------
// Persistent Sinkhorn kernel: init + 100 iterations + final cost, 1 launch.
// ---------------------------------------------------------------------------
__global__ void __launch_bounds__(1024, 1) k_sink(float* __restrict__ out) {
    __shared__ float ws[1024];
    __shared__ float du_s[128];
    int tid  = threadIdx.x, bid = blockIdx.x;
    int lane = tid & 31,    wid = tid >> 5;

    // re-init per graph replay
    if (tid < 128) { int r = (bid << 7) + tid; g_u[r] = 0.f; g_v[r] = 0.f; }
    if (bid == 0 && tid == 0) g_done = 0;
    gbarrier();

    for (int it = 0; it < 100; it++) {
        int done = *(volatile int*)&g_done;     // frozen once latched (ref semantics)
        if (!done)
            scan_phase<true >(bid, tid, lane, wid, g_Ch,  g_C,  g_v, g_u, ws, du_s);
        gbarrier();
        if (!done) {
            if (bid == 0 && wid == 0) {         // err from this iteration's du
                float e = g_bp[lane] + g_bp[lane + 32] + g_bp[lane + 64] + g_bp[lane + 96];
                e = wred_sum(e);
                if (lane == 0 && e * (1.0f / 16.0f) < 0.1f) g_done = 1;
            }
            // triggering iteration's v-update still applied (matches reference)
            scan_phase<false>(bid, tid, lane, wid, g_CTh, g_CT, g_u, g_v, ws, du_s);
        }
        gbarrier();
    }

    // --------- final: sum_ij exp((u_i + v_j - C_ij)/eps) * C_ij ----------
    {
        int b = bid >> 3;
        ws[tid] = g_v[(b << 10) + tid];
        __syncthreads();
        const float4* ws4 = (const float4*)ws;
        half2 w2[16];
        BUILD_W2();

#pragma unroll 1
        for (int r = 0; r < 4; r++) {
            int rl  = (wid << 2) + r;
            int row = (bid << 7) + rl;
            const uint4*  cp  = (const uint4*) (g_Ch + ((size_t)row << 10));
            const float4* cf4 = (const float4*)(g_C  + ((size_t)row << 10));
            float uk = g_u[row];

            float gm0, gm1, gm2, gm3;
            PREF_GRP(0, gm0); PREF_GRP(1, gm1); PREF_GRP(2, gm2); PREF_GRP(3, gm3);

            // contribute iff exp2 exponent > -40 bits; fp16 margin folded in
            float cut = -0.65f - uk;
            int msk = (gm0 > cut) | ((gm1 > cut) << 1) | ((gm2 > cut) << 2) | ((gm3 > cut) << 3);

            float s = 0.f;
#pragma unroll 1
            for (int q = 0; q < 4; q++) if ((msk >> q) & 1) {
                int ix = (q << 6) + (lane << 1);
                float4 a  = cf4[ix],  bb = cf4[ix + 1];
                float4 wa = ws4[ix],  wb = ws4[ix + 1];
                s += exp2f((wa.x - a.x  + uk) * K2F) * a.x
                   + exp2f((wa.y - a.y  + uk) * K2F) * a.y
                   + exp2f((wa.z - a.z  + uk) * K2F) * a.z
                   + exp2f((wa.w - a.w  + uk) * K2F) * a.w
                   + exp2f((wb.x - bb.x + uk) * K2F) * bb.x
                   + exp2f((wb.y - bb.y + uk) * K2F) * bb.y
                   + exp2f((wb.z - bb.z + uk) * K2F) * bb.z
                   + exp2f((wb.w - bb.w + uk) * K2F) * bb.w;
            }
            s = wred_sum(s);
            if (lane == 0) du_s[rl] = s;
        }
        __syncthreads();
        if (wid == 0) {
            float e = du_s[lane] + du_s[lane + 32] + du_s[lane + 64] + du_s[lane + 96];
            e = wred_sum(e);
            if (lane == 0) g_bp[bid] = e;
        }
    }
    gbarrier();
    if (bid == 0 && wid == 0) {
        float e = g_bp[lane] + g_bp[lane + 32] + g_bp[lane + 64] + g_bp[lane + 96];
        e = wred_sum(e);
        if (lane == 0) out[0] = e * (1.0f / 16.0f);   // mean over B
    }
}

// ---------------------------------------------------------------------------
extern "C" void kernel_launch(void* const* d_in, const int* in_sizes, int n_in,
                              void* d_out, int out_size) {
    (void)in_sizes; (void)n_in; (void)out_size;
    const float* X = (const float*)d_in[0];   // output [16,1024,32]
    const float* Y = (const float*)d_in[1];   // labels [16,1024,32]

    k_cost<<<16384, 256>>>(X, Y);
    k_sink<<<NBLK, 1024>>>((float*)d_out);
}